// round 17
// baseline (speedup 1.0000x reference)
#include <cuda_runtime.h>

#define T_WARM 48
#define OUT_STEPS 24
#define UNITS 32
#define NTHREADS 128          // 4 warps
#define WARPS (NTHREADS / 32)
#define BPW 6                 // batch elements per warp (ILP)
#define BPB (WARPS * BPW)     // 24 batches per block

typedef unsigned long long u64;

__device__ __forceinline__ u64 pack2(float lo, float hi) {
    u64 r; asm("mov.b64 %0, {%1, %2};" : "=l"(r) : "f"(lo), "f"(hi)); return r;
}
__device__ __forceinline__ u64 fma2(u64 a, u64 b, u64 c) {
    u64 d; asm("fma.rn.f32x2 %0, %1, %2, %3;" : "=l"(d) : "l"(a), "l"(b), "l"(c)); return d;
}
__device__ __forceinline__ float hadd2(u64 v) {
    float lo, hi; asm("mov.b64 {%0, %1}, %2;" : "=f"(lo), "=f"(hi) : "l"(v));
    return lo + hi;
}
// Hardware tanh (MUFU.TANH).
__device__ __forceinline__ float tanh_hw(float x) {
    float r; asm("tanh.approx.f32 %0, %1;" : "=f"(r) : "f"(x)); return r;
}
// Sigmoid with the 0.5 input scaling pre-folded into the weights:
// z' = 0.5*z  ->  sigmoid(z) = 0.5*tanh(z') + 0.5.
__device__ __forceinline__ float sigmoid_pre(float zp) {
    return fmaf(0.5f, tanh_hw(zp), 0.5f);
}

// One step for all BPW batch elements of this warp. Weights in registers,
// shared across batches. h via per-warp smem (one base pointer, constant
// per-batch offsets -> LDS immediate addressing, no pointer arrays).
__device__ __forceinline__ void stepN(const float (&xin)[BPW],
                                      const u64 (&wi)[16], const u64 (&wf)[16],
                                      const u64 (&wg)[16], const u64 (&wq)[16],
                                      u64 wxi2, u64 wxf2, u64 wxg2, u64 wxo2,
                                      u64 bi2,  u64 bf2,  u64 bg2,  u64 bo2,
                                      const float* __restrict__ hr0,
                                      float* __restrict__ hw0,
                                      float (&h)[BPW], float (&c)[BPW], int lane)
{
    __syncwarp();                       // previous step's STS visible
    u64 ai[BPW], af[BPW], ag[BPW], ao[BPW];
    #pragma unroll
    for (int u = 0; u < BPW; u++) {
        u64 xs = pack2(xin[u], xin[u]);
        ai[u] = fma2(xs, wxi2, bi2);    // (x*wx'+b', 0) folded into acc init
        af[u] = fma2(xs, wxf2, bf2);
        ag[u] = fma2(xs, wxg2, bg2);
        ao[u] = fma2(xs, wxo2, bo2);
    }
    #pragma unroll
    for (int q = 0; q < 8; q++) {
        #pragma unroll
        for (int u = 0; u < BPW; u++) {
            ulonglong2 v = ((const ulonglong2*)(hr0 + u * 32))[q];  // 4 h values
            ai[u] = fma2(v.x, wi[2*q], ai[u]);  ai[u] = fma2(v.y, wi[2*q+1], ai[u]);
            af[u] = fma2(v.x, wf[2*q], af[u]);  af[u] = fma2(v.y, wf[2*q+1], af[u]);
            ag[u] = fma2(v.x, wg[2*q], ag[u]);  ag[u] = fma2(v.y, wg[2*q+1], ag[u]);
            ao[u] = fma2(v.x, wq[2*q], ao[u]);  ao[u] = fma2(v.y, wq[2*q+1], ao[u]);
        }
    }
    #pragma unroll
    for (int u = 0; u < BPW; u++) {
        float ig = sigmoid_pre(hadd2(ai[u]));
        float fg = sigmoid_pre(hadd2(af[u]));
        float gg = tanh_hw(hadd2(ag[u]));
        float og = sigmoid_pre(hadd2(ao[u]));
        c[u] = fmaf(fg, c[u], ig * gg);
        h[u] = og * tanh_hw(c[u]);
        hw0[u * 32 + lane] = h[u];      // STS.32 into the other parity slot
    }
}

__device__ __forceinline__ float warp_proj(float h, float wo, float bo) {
    float v = h * wo;
    v += __shfl_xor_sync(0xffffffffu, v, 16);
    v += __shfl_xor_sync(0xffffffffu, v, 8);
    v += __shfl_xor_sync(0xffffffffu, v, 4);
    v += __shfl_xor_sync(0xffffffffu, v, 2);
    v += __shfl_xor_sync(0xffffffffu, v, 1);
    return v + bo;
}

__global__ void __launch_bounds__(NTHREADS, 2)
feedback_lstm_kernel(const float* __restrict__ X,
                     const float* __restrict__ Wkw, const float* __restrict__ Ukw,
                     const float* __restrict__ bw,
                     const float* __restrict__ Wkd, const float* __restrict__ Ukd,
                     const float* __restrict__ bdv,
                     const float* __restrict__ Wd,  const float* __restrict__ bd,
                     float* __restrict__ out, int Bn)
{
    __shared__ float sU0[32 * 128];
    __shared__ float sU1[32 * 128];
    __shared__ float sWx0[128], sWx1[128], sB0[128], sB1[128];
    __shared__ float sWo[UNITS];
    __shared__ float sbo;
    __shared__ __align__(16) float hbuf[2][WARPS][BPW][32];
    __shared__ float sX[BPB][T_WARM];

    const int tid = threadIdx.x;
    #pragma unroll 4
    for (int i = tid; i < 32 * 128; i += NTHREADS) {
        sU0[i] = Ukw[i];
        sU1[i] = Ukd[i];
    }
    if (tid < 128) {
        sWx0[tid] = Wkw[tid];
        sB0[tid]  = bw[tid];
        sWx1[tid] = Wkd[tid];
        sB1[tid]  = bdv[tid];
    }
    if (tid < UNITS) sWo[tid] = Wd[tid];
    if (tid == 0) sbo = bd[0];

    // Stage this block's BPB input rows (coalesced); clamp reads on the
    // (single) partial tail block.
    const long base = (long)blockIdx.x * BPB;
    for (int i = tid; i < BPB * T_WARM; i += NTHREADS) {
        int bb = i / T_WARM, t = i % T_WARM;
        long row = base + bb; if (row > Bn - 1) row = Bn - 1;
        sX[bb][t] = X[row * T_WARM + t];
    }
    __syncthreads();

    const int lane = tid & 31;
    const int warp = tid >> 5;
    const float wo = sWo[lane];
    const float bo = sbo;

    float h[BPW], c[BPW];
    #pragma unroll
    for (int u = 0; u < BPW; u++) {
        h[u] = 0.f; c[u] = 0.f;
        hbuf[0][warp][u][lane] = 0.f;
    }
    int par = 0;

    // ---- Phase 1: warmup, warm weights in registers ----
    // wi[m] = (U[2m][j], U[2m+1][j]) for this lane's unit j, per gate.
    // i/f/o gate weights (incl. wx, b) pre-scaled by 0.5 for sigmoid_pre.
    u64 wi[16], wf[16], wg[16], wq[16];
    u64 wxi2, wxf2, wxg2, wxo2, bi2, bf2, bg2, bo2;
    #pragma unroll
    for (int m = 0; m < 16; m++) {
        wi[m] = pack2(0.5f * sU0[(2*m) * 128 + lane],      0.5f * sU0[(2*m+1) * 128 + lane]);
        wf[m] = pack2(0.5f * sU0[(2*m) * 128 + 32 + lane], 0.5f * sU0[(2*m+1) * 128 + 32 + lane]);
        wg[m] = pack2(       sU0[(2*m) * 128 + 64 + lane],        sU0[(2*m+1) * 128 + 64 + lane]);
        wq[m] = pack2(0.5f * sU0[(2*m) * 128 + 96 + lane], 0.5f * sU0[(2*m+1) * 128 + 96 + lane]);
    }
    wxi2 = pack2(0.5f * sWx0[lane],      0.f);  bi2 = pack2(0.5f * sB0[lane],      0.f);
    wxf2 = pack2(0.5f * sWx0[32 + lane], 0.f);  bf2 = pack2(0.5f * sB0[32 + lane], 0.f);
    wxg2 = pack2(       sWx0[64 + lane], 0.f);  bg2 = pack2(       sB0[64 + lane], 0.f);
    wxo2 = pack2(0.5f * sWx0[96 + lane], 0.f);  bo2 = pack2(0.5f * sB0[96 + lane], 0.f);

    for (int t = 0; t < T_WARM; t++) {
        float xin[BPW];
        #pragma unroll
        for (int u = 0; u < BPW; u++) xin[u] = sX[warp * BPW + u][t];
        stepN(xin, wi, wf, wg, wq, wxi2, wxf2, wxg2, wxo2,
              bi2, bf2, bg2, bo2,
              &hbuf[par][warp][0][0], &hbuf[par ^ 1][warp][0][0],
              h, c, lane);
        par ^= 1;
    }

    float p[BPW], myp[BPW];
    #pragma unroll
    for (int u = 0; u < BPW; u++) {
        p[u] = warp_proj(h[u], wo, bo);
        myp[u] = p[u];
    }

    // ---- Phase 2: decode, reload registers with decode weights ----
    #pragma unroll
    for (int m = 0; m < 16; m++) {
        wi[m] = pack2(0.5f * sU1[(2*m) * 128 + lane],      0.5f * sU1[(2*m+1) * 128 + lane]);
        wf[m] = pack2(0.5f * sU1[(2*m) * 128 + 32 + lane], 0.5f * sU1[(2*m+1) * 128 + 32 + lane]);
        wg[m] = pack2(       sU1[(2*m) * 128 + 64 + lane],        sU1[(2*m+1) * 128 + 64 + lane]);
        wq[m] = pack2(0.5f * sU1[(2*m) * 128 + 96 + lane], 0.5f * sU1[(2*m+1) * 128 + 96 + lane]);
    }
    wxi2 = pack2(0.5f * sWx1[lane],      0.f);  bi2 = pack2(0.5f * sB1[lane],      0.f);
    wxf2 = pack2(0.5f * sWx1[32 + lane], 0.f);  bf2 = pack2(0.5f * sB1[32 + lane], 0.f);
    wxg2 = pack2(       sWx1[64 + lane], 0.f);  bg2 = pack2(       sB1[64 + lane], 0.f);
    wxo2 = pack2(0.5f * sWx1[96 + lane], 0.f);  bo2 = pack2(0.5f * sB1[96 + lane], 0.f);

    for (int s = 1; s < OUT_STEPS; s++) {
        float xin[BPW];
        #pragma unroll
        for (int u = 0; u < BPW; u++) xin[u] = p[u];
        stepN(xin, wi, wf, wg, wq, wxi2, wxf2, wxg2, wxo2,
              bi2, bf2, bg2, bo2,
              &hbuf[par][warp][0][0], &hbuf[par ^ 1][warp][0][0],
              h, c, lane);
        par ^= 1;
        #pragma unroll
        for (int u = 0; u < BPW; u++) {
            p[u] = warp_proj(h[u], wo, bo);
            if (lane == s) myp[u] = p[u];
        }
    }

    if (lane < OUT_STEPS) {
        #pragma unroll
        for (int u = 0; u < BPW; u++) {
            long row = base + warp * BPW + u;
            if (row < Bn) out[row * OUT_STEPS + lane] = myp[u];
        }
    }
}

extern "C" void kernel_launch(void* const* d_in, const int* in_sizes, int n_in,
                              void* d_out, int out_size) {
    const float* X   = (const float*)d_in[0];
    const float* Wkw = (const float*)d_in[1];
    const float* Ukw = (const float*)d_in[2];
    const float* bw  = (const float*)d_in[3];
    const float* Wkd = (const float*)d_in[4];
    const float* Ukd = (const float*)d_in[5];
    const float* bdv = (const float*)d_in[6];
    const float* Wd  = (const float*)d_in[7];
    const float* bd  = (const float*)d_in[8];
    float* out = (float*)d_out;

    int Bn = in_sizes[0] / T_WARM;            // F == 1
    int grid = (Bn + BPB - 1) / BPB;
    feedback_lstm_kernel<<<grid, NTHREADS>>>(X, Wkw, Ukw, bw, Wkd, Ukd, bdv, Wd, bd, out, Bn);
}